// round 4
// baseline (speedup 1.0000x reference)
#include <cuda_runtime.h>
#include <math.h>

#define BB 4
#define CC 64
#define NN 4096
#define INTER 16

// ---------------- scratch (device globals; no allocations allowed) ----------
__device__ double g_wa[CC], g_wd[CC];
__device__ double g_ca, g_cd;
__device__ __align__(16) float g_WvgT[CC * CC];   // [cin][o]
__device__ float g_bvg[CC];
__device__ float g_a[BB * NN];
__device__ float g_d[BB * NN];
__device__ double g_dd[BB * NN];                    // double-precision d
__device__ __align__(16) float g_vp[BB * NN * CC];  // [b][n][c]
__device__ float g_s[BB * NN];                       // sorted a (ascending)
__device__ int   g_idx[BB * NN];                     // permutation
__device__ float g_Pva[BB * (NN + 1) * CC];          // prefix of v*a, [b][r][c]
__device__ float g_Pv [BB * (NN + 1) * CC];          // prefix of v
__device__ float g_Pve[BB * (NN + 1) * CC];          // prefix of v*exp(a)
__device__ double g_Pa[BB * (NN + 1)];               // prefix of a (double)
__device__ double g_Pe[BB * (NN + 1)];               // prefix of exp(a) (double)

// ---------------- K1: fold weights (double for the a/d path) -------------
__global__ void k1_precompute(const float* __restrict__ Wq, const float* __restrict__ bq,
                              const float* __restrict__ Wk, const float* __restrict__ bk,
                              const float* __restrict__ wcq, const float* __restrict__ wck,
                              const float* __restrict__ Wv, const float* __restrict__ bv,
                              const float* __restrict__ Wg) {
    int t = threadIdx.x;  // 256
    if (t < CC) {
        double sa = 0.0, sd = 0.0;
        for (int i = 0; i < INTER; i++) {
            sa += (double)wcq[i] * (double)Wq[i * CC + t];
            sd += (double)wck[i] * (double)Wk[i * CC + t];
        }
        g_wa[t] = sa;
        g_wd[t] = sd;
    }
    if (t >= 64 && t < 128) {
        int o = t - 64;
        float s = 0.f;
        for (int m = 0; m < CC; m++) s += Wg[o * CC + m] * bv[m];
        g_bvg[o] = s;
    }
    if (t == 128) {
        double ca = 0.0, cd = 0.0;
        for (int i = 0; i < INTER; i++) {
            ca += (double)wcq[i] * (double)bq[i];
            cd += (double)wck[i] * (double)bk[i];
        }
        g_ca = ca;
        g_cd = cd;
    }
    for (int e = t; e < CC * CC; e += 256) {
        int cin = e / CC, o = e % CC;
        float s = 0.f;
        for (int m = 0; m < CC; m++) s += Wg[o * CC + m] * Wv[m * CC + cin];
        g_WvgT[cin * CC + o] = s;
    }
}

// ---------------- K2: per-pixel projections a, d, v' ---------------------
__global__ void k2_proj(const float* __restrict__ x) {
    __shared__ __align__(16) float shW[CC * CC];
    __shared__ double shwa[CC], shwd[CC];
    __shared__ float shb[CC];
    int tid = threadIdx.x;  // 128
    for (int e = tid; e < CC * CC; e += 128) shW[e] = g_WvgT[e];
    if (tid < CC) { shwa[tid] = g_wa[tid]; shwd[tid] = g_wd[tid]; shb[tid] = g_bvg[tid]; }
    __syncthreads();

    int g = blockIdx.x * 128 + tid;  // 0 .. B*N-1
    int b = g / NN, n = g % NN;
    const float* xb = x + (size_t)b * CC * NN + n;

    float acc[CC];
#pragma unroll
    for (int o = 0; o < CC; o++) acc[o] = shb[o];
    double aa = g_ca, dd = g_cd;

    for (int cin = 0; cin < CC; cin++) {
        float xv = xb[(size_t)cin * NN];
        aa += shwa[cin] * (double)xv;
        dd += shwd[cin] * (double)xv;
        const float4* wrow = (const float4*)&shW[cin * CC];
#pragma unroll
        for (int o4 = 0; o4 < CC / 4; o4++) {
            float4 w = wrow[o4];
            acc[o4 * 4 + 0] += w.x * xv;
            acc[o4 * 4 + 1] += w.y * xv;
            acc[o4 * 4 + 2] += w.z * xv;
            acc[o4 * 4 + 3] += w.w * xv;
        }
    }
    g_a[g] = (float)aa;
    g_d[g] = (float)dd;
    g_dd[g] = dd;
    float4* vout = (float4*)&g_vp[(size_t)g * CC];
#pragma unroll
    for (int o4 = 0; o4 < CC / 4; o4++)
        vout[o4] = make_float4(acc[o4 * 4 + 0], acc[o4 * 4 + 1], acc[o4 * 4 + 2], acc[o4 * 4 + 3]);
}

// ---------------- K3: per-batch bitonic sort of a (ascending) ------------
__global__ void k3_sort() {
    __shared__ float sv[NN];
    __shared__ int si[NN];
    int b = blockIdx.x;
    int tid = threadIdx.x;  // 1024
    for (int e = tid; e < NN; e += 1024) { sv[e] = g_a[b * NN + e]; si[e] = e; }
    __syncthreads();
    for (int k = 2; k <= NN; k <<= 1) {
        for (int j = k >> 1; j > 0; j >>= 1) {
            for (int e = tid; e < NN; e += 1024) {
                int ixj = e ^ j;
                if (ixj > e) {
                    bool up = ((e & k) == 0);
                    float a0 = sv[e], a1 = sv[ixj];
                    if ((a0 > a1) == up) {
                        sv[e] = a1; sv[ixj] = a0;
                        int i0 = si[e]; si[e] = si[ixj]; si[ixj] = i0;
                    }
                }
            }
            __syncthreads();
        }
    }
    for (int e = tid; e < NN; e += 1024) { g_s[b * NN + e] = sv[e]; g_idx[b * NN + e] = si[e]; }
}

// ---------------- K4: prefix scans over sorted order ---------------------
// grid = B*(C+1); block 256, each thread owns 16 consecutive ranks.
// c < C : streams (v*a, v, v*exp(a)) -> Pva, Pv, Pve (fp32 out, fp64 accum)
// c == C: streams (a, exp(a))        -> Pa, Pe      (fp64 out)
__global__ void k4_scan() {
    __shared__ double sh0[256], sh1[256], sh2[256];
    int blk = blockIdx.x;
    int b = blk / (CC + 1);
    int c = blk % (CC + 1);
    int tid = threadIdx.x;
    int r0 = tid * 16;
    const float* s = &g_s[b * NN];
    const int* idx = &g_idx[b * NN];

    double l0 = 0.0, l1 = 0.0, l2 = 0.0;
    if (c < CC) {
        for (int u = 0; u < 16; u++) {
            int r = r0 + u;
            float sval = s[r];
            float f = g_vp[((size_t)b * NN + idx[r]) * CC + c];
            l0 += (double)f * (double)sval;
            l1 += (double)f;
            l2 += (double)f * (double)expf(sval);
        }
    } else {
        for (int u = 0; u < 16; u++) {
            float sval = s[r0 + u];
            l0 += (double)sval;
            l1 += exp((double)sval);
        }
    }
    sh0[tid] = l0; sh1[tid] = l1; sh2[tid] = l2;
    __syncthreads();
    for (int off = 1; off < 256; off <<= 1) {
        double t0 = 0, t1 = 0, t2 = 0;
        if (tid >= off) { t0 = sh0[tid - off]; t1 = sh1[tid - off]; t2 = sh2[tid - off]; }
        __syncthreads();
        sh0[tid] += t0; sh1[tid] += t1; sh2[tid] += t2;
        __syncthreads();
    }
    double b0 = 0, b1 = 0, b2 = 0;
    if (tid > 0) { b0 = sh0[tid - 1]; b1 = sh1[tid - 1]; b2 = sh2[tid - 1]; }

    if (c < CC) {
        size_t base = ((size_t)b * (NN + 1)) * CC + c;
        if (tid == 0) { g_Pva[base] = 0.f; g_Pv[base] = 0.f; g_Pve[base] = 0.f; }
        double r0d = b0, r1d = b1, r2d = b2;
        for (int u = 0; u < 16; u++) {
            int r = r0 + u;
            float sval = s[r];
            float f = g_vp[((size_t)b * NN + idx[r]) * CC + c];
            r0d += (double)f * (double)sval;
            r1d += (double)f;
            r2d += (double)f * (double)expf(sval);
            size_t o = base + (size_t)(r + 1) * CC;
            g_Pva[o] = (float)r0d;
            g_Pv[o]  = (float)r1d;
            g_Pve[o] = (float)r2d;
        }
    } else {
        size_t base = (size_t)b * (NN + 1);
        if (tid == 0) { g_Pa[base] = 0.0; g_Pe[base] = 0.0; }
        double r0d = b0, r1d = b1;
        for (int u = 0; u < 16; u++) {
            int r = r0 + u;
            float sval = s[r];
            r0d += (double)sval;
            r1d += exp((double)sval);
            g_Pa[base + r + 1] = r0d;
            g_Pe[base + r + 1] = r1d;
        }
    }
}

// ---------------- K5: per-column output ----------------------------------
__global__ void k5_out(const float* __restrict__ bg, float* __restrict__ out) {
    __shared__ float sh_s[NN];                       // 16KB
    __shared__ float sh_tva[CC], sh_tv[CC], sh_bg[CC];
    int blk = blockIdx.x;  // B*16
    int b = blk / 16;
    int jbase = (blk % 16) * 256;
    int tid = threadIdx.x;  // 256
    for (int e = tid; e < NN; e += 256) sh_s[e] = g_s[b * NN + e];
    if (tid < CC) {
        size_t totrow = ((size_t)b * (NN + 1) + NN) * CC;
        sh_tva[tid] = g_Pva[totrow + tid];
        sh_tv[tid]  = g_Pv[totrow + tid];
        sh_bg[tid]  = bg[tid];
    }
    __syncthreads();

    int j = jbase + tid;
    double djd = g_dd[b * NN + j];
    float dj = (float)djd;
    float t = (float)(-djd);
    // r = count of sorted a_i <= t  (exp branch set)
    int lo = 0, hi = NN;
    while (lo < hi) {
        int mid = (lo + hi) >> 1;
        if (sh_s[mid] <= t) lo = mid + 1; else hi = mid;
    }
    int r = lo;
    double edd = exp(djd);
    float ed = (float)edd;

    // S in full double precision (singular columns amplify any S error)
    size_t sbase = (size_t)b * (NN + 1);
    double SaN = g_Pa[sbase + NN];
    double S = (SaN - g_Pa[sbase + r]) + (double)(NN - r) * djd
             + edd * g_Pe[sbase + r] - (double)r;
    float inv = (float)(1.0 / (1.5 * S));

    size_t rowr = ((size_t)b * (NN + 1) + r) * CC;
    float* ob = out + (size_t)b * CC * NN + j;
#pragma unroll 4
    for (int c = 0; c < CC; c++) {
        float pva = g_Pva[rowr + c];
        float pv  = g_Pv[rowr + c];
        float pve = g_Pve[rowr + c];
        float num = (sh_tva[c] - pva) + dj * (sh_tv[c] - pv) + ed * pve - pv;
        ob[(size_t)c * NN] = inv * num + sh_bg[c];
    }
}

// ---------------- launcher ----------------------------------------------
extern "C" void kernel_launch(void* const* d_in, const int* in_sizes, int n_in,
                              void* d_out, int out_size) {
    const float* x   = (const float*)d_in[0];
    const float* Wq  = (const float*)d_in[1];
    const float* bq  = (const float*)d_in[2];
    const float* Wk  = (const float*)d_in[3];
    const float* bk  = (const float*)d_in[4];
    const float* wcq = (const float*)d_in[5];
    const float* wck = (const float*)d_in[6];
    const float* Wv  = (const float*)d_in[7];
    const float* bv  = (const float*)d_in[8];
    const float* Wg  = (const float*)d_in[9];
    const float* bg  = (const float*)d_in[10];
    float* out = (float*)d_out;

    k1_precompute<<<1, 256>>>(Wq, bq, Wk, bk, wcq, wck, Wv, bv, Wg);
    k2_proj<<<(BB * NN) / 128, 128>>>(x);
    k3_sort<<<BB, 1024>>>();
    k4_scan<<<BB * (CC + 1), 256>>>();
    k5_out<<<BB * 16, 256>>>(bg, out);
}